// round 3
// baseline (speedup 1.0000x reference)
#include <cuda_runtime.h>

// ChamferDistance via uniform-grid exact nearest neighbor.
// B=8, N=M=8192, D=3, points ~ N(0,1).
// Grid: 64^3 over [-6,6]^3 per (batch, set). Counting sort both sets, then
// each point ring-searches the opposing grid; exact termination when
// best <= (r*cellw)^2. Result = (sum of all mins)/65536.

#define BATCH 8
#define PTS   8192
#define SEG   16                        // batch*2 + (0=x, 1=y)
#define G     64
#define CELLS (G*G*G)                   // 262144 (one z-slice = 4096 cells)
#define TOTCELLS (SEG*CELLS)            // 4,194,304
#define SCAN_TPB 512
#define CPT   8                         // cells per scan thread
#define SCAN_BLK_CELLS (SCAN_TPB*CPT)   // 4096 = 2^12
#define NSCANBLK (TOTCELLS/SCAN_BLK_CELLS) // 1024
#define BOXMIN (-6.0f)
#define INVW   (G/12.0f)
#define CELLW  (12.0f/G)

__device__ __align__(16) unsigned g_cnt[TOTCELLS];
__device__ __align__(16) unsigned g_cur[TOTCELLS];
__device__ unsigned g_off[TOTCELLS];    // per-scan-block exclusive scan
__device__ unsigned g_tot[NSCANBLK];    // per-scan-block totals
__device__ unsigned g_base[NSCANBLK];   // exclusive scan of totals (per segment)
__device__ float4   g_sorted[SEG*PTS];  // (x,y,z, orig_idx bits)
__device__ float    g_min[SEG*PTS];
__device__ float    g_part[256];

__device__ __forceinline__ int cell_coord(float v) {
    int c = (int)floorf((v - BOXMIN) * INVW);
    return min(max(c, 0), G - 1);
}

// ---- 1. clear counts + cursors ----
__global__ __launch_bounds__(256)
void k_clear() {
    int i = blockIdx.x * 256 + threadIdx.x;     // TOTCELLS/4 threads
    ((uint4*)g_cnt)[i] = make_uint4(0, 0, 0, 0);
    ((uint4*)g_cur)[i] = make_uint4(0, 0, 0, 0);
}

// ---- 2. count points per cell ----
__global__ __launch_bounds__(256)
void k_count(const float* __restrict__ x, const float* __restrict__ y) {
    int g = blockIdx.x * 256 + threadIdx.x;     // SEG*PTS threads
    int seg = g >> 13, i = g & (PTS - 1);
    int b = seg >> 1;
    const float* src = (seg & 1) ? y : x;
    const float* p = src + ((size_t)b * PTS + i) * 3;
    int c = (cell_coord(p[2]) * G + cell_coord(p[1])) * G + cell_coord(p[0]);
    atomicAdd(&g_cnt[seg * CELLS + c], 1u);
}

// ---- 3. per-block exclusive scan (4096 cells per block) ----
__global__ __launch_bounds__(SCAN_TPB)
void k_scan1() {
    __shared__ unsigned s[SCAN_TPB];
    int tid = threadIdx.x;
    int base = blockIdx.x * SCAN_BLK_CELLS + tid * CPT;
    unsigned v[CPT], run = 0;
#pragma unroll
    for (int k = 0; k < CPT; k++) { v[k] = run; run += g_cnt[base + k]; }
    s[tid] = run;
    __syncthreads();
#pragma unroll
    for (int off = 1; off < SCAN_TPB; off <<= 1) {
        unsigned t = (tid >= off) ? s[tid - off] : 0u;
        __syncthreads();
        if (tid >= off) s[tid] += t;
        __syncthreads();
    }
    unsigned prefix = s[tid] - run;   // exclusive prefix of this thread
#pragma unroll
    for (int k = 0; k < CPT; k++) g_off[base + k] = prefix + v[k];
    if (tid == SCAN_TPB - 1) g_tot[blockIdx.x] = s[SCAN_TPB - 1];
}

// ---- 4. scan of block totals, per segment (64 blocks/segment) ----
__global__ __launch_bounds__(64)
void k_scan2() {
    __shared__ unsigned s[64];
    int seg = blockIdx.x, tid = threadIdx.x;
    unsigned v = g_tot[seg * 64 + tid];
    s[tid] = v;
    __syncthreads();
#pragma unroll
    for (int off = 1; off < 64; off <<= 1) {
        unsigned t = (tid >= off) ? s[tid - off] : 0u;
        __syncthreads();
        if (tid >= off) s[tid] += t;
        __syncthreads();
    }
    g_base[seg * 64 + tid] = s[tid] - v;
}

// ---- 5. scatter points into cell-sorted order ----
__global__ __launch_bounds__(256)
void k_scatter(const float* __restrict__ x, const float* __restrict__ y) {
    int g = blockIdx.x * 256 + threadIdx.x;
    int seg = g >> 13, i = g & (PTS - 1);
    int b = seg >> 1;
    const float* src = (seg & 1) ? y : x;
    const float* p = src + ((size_t)b * PTS + i) * 3;
    float px = p[0], py = p[1], pz = p[2];
    int c = (cell_coord(pz) * G + cell_coord(py)) * G + cell_coord(px);
    unsigned gc = seg * CELLS + c;
    unsigned pos = g_off[gc] + g_base[gc >> 12] + atomicAdd(&g_cur[gc], 1u);
    g_sorted[seg * PTS + pos] = make_float4(px, py, pz, __int_as_float(i));
}

// ---- 6. ring-search query ----
__global__ __launch_bounds__(256)
void k_query() {
    int g = blockIdx.x * 256 + threadIdx.x;
    int seg_q = g >> 13, slot = g & (PTS - 1);
    int seg_t = seg_q ^ 1;

    float4 q = g_sorted[seg_q * PTS + slot];
    const unsigned tbase = seg_t * CELLS;
    const float4* __restrict__ tp = g_sorted + seg_t * PTS;

    int cx = cell_coord(q.x), cy = cell_coord(q.y), cz = cell_coord(q.z);
    float best = 3.4e38f;

    auto row = [&](int z, int yy, int x0, int x1) {
        x0 = max(x0, 0); x1 = min(x1, G - 1);
        if (x0 > x1) return;
        int c0 = (z * G + yy) * G + x0;
        unsigned gc0 = tbase + c0;
        unsigned gce = gc0 + (unsigned)(x1 - x0);
        unsigned s = g_off[gc0] + g_base[gc0 >> 12];
        unsigned e = g_off[gce] + g_base[gce >> 12] + g_cnt[gce];
        for (unsigned p = s; p < e; p++) {
            float4 t = tp[p];
            float dx = q.x - t.x, dy = q.y - t.y, dz = q.z - t.z;
            float d = fmaf(dx, dx, fmaf(dy, dy, dz * dz));
            best = fminf(best, d);
        }
    };

    for (int r = 0; r < G; r++) {
        for (int dz = -r; dz <= r; dz++) {
            int z = cz + dz;
            if ((unsigned)z >= G) continue;
            bool zface = (dz == -r) || (dz == r);
            for (int dy = -r; dy <= r; dy++) {
                int yy = cy + dy;
                if ((unsigned)yy >= G) continue;
                if (zface || dy == -r || dy == r) {
                    row(z, yy, cx - r, cx + r);
                } else {
                    row(z, yy, cx - r, cx - r);
                    row(z, yy, cx + r, cx + r);
                }
            }
        }
        float bound = r * CELLW;
        if (best <= bound * bound) break;
    }

    g_min[seg_q * PTS + __float_as_int(q.w)] = best;
}

// ---- 7/8. deterministic reductions ----
__global__ __launch_bounds__(256)
void k_reduce1() {
    __shared__ float red[256];
    int tid = threadIdx.x;
    int i0 = blockIdx.x * 512 + tid;
    red[tid] = g_min[i0] + g_min[i0 + 256];
    __syncthreads();
#pragma unroll
    for (int off = 128; off > 0; off >>= 1) {
        if (tid < off) red[tid] += red[tid + off];
        __syncthreads();
    }
    if (tid == 0) g_part[blockIdx.x] = red[0];
}

__global__ __launch_bounds__(256)
void k_reduce2(float* __restrict__ out) {
    __shared__ float red[256];
    int tid = threadIdx.x;
    red[tid] = g_part[tid];
    __syncthreads();
#pragma unroll
    for (int off = 128; off > 0; off >>= 1) {
        if (tid < off) red[tid] += red[tid + off];
        __syncthreads();
    }
    if (tid == 0) out[0] = red[0] * (1.0f / 65536.0f);
}

extern "C" void kernel_launch(void* const* d_in, const int* in_sizes, int n_in,
                              void* d_out, int out_size) {
    const float* x = (const float*)d_in[0];
    const float* y = (const float*)d_in[1];
    float* out = (float*)d_out;

    k_clear  <<<TOTCELLS / 4 / 256, 256>>>();
    k_count  <<<SEG * PTS / 256, 256>>>(x, y);
    k_scan1  <<<NSCANBLK, SCAN_TPB>>>();
    k_scan2  <<<SEG, 64>>>();
    k_scatter<<<SEG * PTS / 256, 256>>>(x, y);
    k_query  <<<SEG * PTS / 256, 256>>>();
    k_reduce1<<<256, 256>>>();
    k_reduce2<<<1, 256>>>(out);
}

// round 5
// speedup vs baseline: 1.3558x; 1.3558x over previous
#include <cuda_runtime.h>

// ChamferDistance via z-sorted slab pruning. B=8, N=M=8192, D=3, x,y ~ N(0,1).
// Counting-sort each (batch,set) segment by z into NB bins; each query expands
// a contiguous window over the opposing sorted array, terminating exactly when
// best <= (distance to unscanned z-region)^2 on both sides.
// out = (sum of all 131072 mins) / 65536.

#define BATCH  8
#define PTS    8192
#define SEG    16                 // (batch<<1) | (0=x set, 1=y set)
#define NB     512
#define BOXMIN (-6.0f)
#define INVW   ((float)NB / 12.0f)
#define WB     (12.0f / (float)NB)

__device__ float4   g_sorted[SEG * PTS];   // (x,y,z, orig idx bits), z-bin sorted
__device__ unsigned g_binoff[SEG * (NB + 1)];
__device__ float    g_min[SEG * PTS];
__device__ unsigned g_ticket = 0;

__device__ __forceinline__ int binof(float z) {
    int b = (int)floorf((z - BOXMIN) * INVW);
    return min(max(b, 0), NB - 1);
}

// ---- 1. per-segment counting sort by z (one block per segment) ----
__global__ __launch_bounds__(256)
void k_sort(const float* __restrict__ x, const float* __restrict__ y) {
    __shared__ unsigned cnt[NB];
    __shared__ unsigned off[NB + 1];
    __shared__ unsigned scn[256];

    const int seg = blockIdx.x;
    const int tid = threadIdx.x;
    const float* __restrict__ src = (seg & 1) ? y : x;
    const float* __restrict__ base = src + (size_t)(seg >> 1) * PTS * 3;

    for (int i = tid; i < NB; i += 256) cnt[i] = 0;
    __syncthreads();

    // histogram
    for (int i = tid; i < PTS; i += 256)
        atomicAdd(&cnt[binof(base[i * 3 + 2])], 1u);
    __syncthreads();

    // exclusive scan of NB=512 bins (2 bins per thread + block scan)
    unsigned v0 = cnt[2 * tid], v1 = cnt[2 * tid + 1];
    unsigned s = v0 + v1;
    scn[tid] = s;
    __syncthreads();
#pragma unroll
    for (int o = 1; o < 256; o <<= 1) {
        unsigned t = (tid >= o) ? scn[tid - o] : 0u;
        __syncthreads();
        if (tid >= o) scn[tid] += t;
        __syncthreads();
    }
    unsigned excl = scn[tid] - s;
    off[2 * tid]     = excl;
    off[2 * tid + 1] = excl + v0;
    if (tid == 255) off[NB] = scn[255];
    __syncthreads();

    // reset cnt as scatter cursor
    for (int i = tid; i < NB; i += 256) cnt[i] = 0;
    __syncthreads();

    // scatter
    for (int i = tid; i < PTS; i += 256) {
        float px = base[i * 3 + 0];
        float py = base[i * 3 + 1];
        float pz = base[i * 3 + 2];
        int b = binof(pz);
        unsigned pos = off[b] + atomicAdd(&cnt[b], 1u);
        g_sorted[seg * PTS + pos] = make_float4(px, py, pz, __int_as_float(i));
    }

    for (int i = tid; i <= NB; i += 256)
        g_binoff[seg * (NB + 1) + i] = off[i];
}

// ---- 2. window-expansion query + deterministic tail reduction ----
__global__ __launch_bounds__(256)
void k_query(float* __restrict__ out) {
    const int g = blockIdx.x * 256 + threadIdx.x;
    const int seg_q = g >> 13, slot = g & (PTS - 1);
    const int seg_t = seg_q ^ 1;

    const float4 q = g_sorted[seg_q * PTS + slot];
    const float4* __restrict__ tp = g_sorted + seg_t * PTS;
    const unsigned* __restrict__ boff = g_binoff + seg_t * (NB + 1);

    const int b = binof(q.z);
    float best = 3.4e38f;

    unsigned lo = boff[b], hi = boff[b + 1];
    for (unsigned p = lo; p < hi; p++) {
        float4 t = tp[p];
        float dx = q.x - t.x, dy = q.y - t.y, dz = q.z - t.z;
        best = fminf(best, fmaf(dx, dx, fmaf(dy, dy, dz * dz)));
    }

    int bL = b, bR = b;
    while (1) {
        float dzlo = q.z - (BOXMIN + bL * WB);          // gap to unscanned low z
        float dzhi = (BOXMIN + (bR + 1) * WB) - q.z;    // gap to unscanned high z
        bool needLo = (bL > 0)      && (best > dzlo * dzlo);
        bool needHi = (bR < NB - 1) && (best > dzhi * dzhi);
        if (!needLo && !needHi) break;
        if (needLo) {
            unsigned nlo = boff[--bL];
            for (unsigned p = nlo; p < lo; p++) {
                float4 t = tp[p];
                float dx = q.x - t.x, dy = q.y - t.y, dz = q.z - t.z;
                best = fminf(best, fmaf(dx, dx, fmaf(dy, dy, dz * dz)));
            }
            lo = nlo;
        }
        if (needHi) {
            unsigned nhi = boff[++bR + 1];
            for (unsigned p = hi; p < nhi; p++) {
                float4 t = tp[p];
                float dx = q.x - t.x, dy = q.y - t.y, dz = q.z - t.z;
                best = fminf(best, fmaf(dx, dx, fmaf(dy, dy, dz * dz)));
            }
            hi = nhi;
        }
    }

    g_min[seg_q * PTS + __float_as_int(q.w)] = best;

    // ---- ticket-gated deterministic reduction by the last block ----
    __shared__ bool isLast;
    __threadfence();
    __syncthreads();
    if (threadIdx.x == 0) {
        unsigned t = atomicAdd(&g_ticket, 1u);
        isLast = (t == gridDim.x - 1);
        if (isLast) g_ticket = 0;   // reset for next graph replay
    }
    __syncthreads();
    if (isLast) {
        __shared__ float red[256];
        const int tid = threadIdx.x;
        float s = 0.0f;
        // fixed ascending order per thread -> deterministic
        for (int i = tid; i < SEG * PTS; i += 256) s += g_min[i];
        red[tid] = s;
        __syncthreads();
#pragma unroll
        for (int o = 128; o > 0; o >>= 1) {
            if (tid < o) red[tid] += red[tid + o];
            __syncthreads();
        }
        if (tid == 0) out[0] = red[0] * (1.0f / 65536.0f);
    }
}

extern "C" void kernel_launch(void* const* d_in, const int* in_sizes, int n_in,
                              void* d_out, int out_size) {
    const float* x = (const float*)d_in[0];
    const float* y = (const float*)d_in[1];
    float* out = (float*)d_out;

    k_sort <<<SEG, 256>>>(x, y);
    k_query<<<SEG * PTS / 256, 256>>>(out);
}

// round 6
// speedup vs baseline: 3.5646x; 2.6290x over previous
#include <cuda_runtime.h>

// ChamferDistance: B=8, N=M=8192, D=3.
// d(i,j) = |x_i|^2 + |y_j|^2 - 2 x_i.y_j
// min_j d = min_j (n_j + x . y'_j) + |x_i|^2, y' = -2y precomputed in tile fill.
// Inner loop on packed fma.rn.f32x2; shared tiles loaded as ulonglong2 so
// operands are born as aligned 64-bit register pairs (no pack MOVs).

#define TPB   256
#define RX    2
#define CHUNK (TPB * RX)          // 512 owned points per block
#define PTS   8192
#define BATCH 8
#define TILE  1024
#define JP    (TILE / 2)          // j-pairs per tile
#define CHUNKS_PER_BATCH (PTS / CHUNK)                  // 16
#define BLOCKS_PER_DIR   (BATCH * CHUNKS_PER_BATCH)     // 128
#define NBLOCKS          (2 * BLOCKS_PER_DIR)           // 256

__device__ float    g_part[NBLOCKS];
__device__ unsigned g_ticket = 0;

#define PACK_F32X2(out, lo, hi) \
    asm("mov.b64 %0, {%1, %2};" : "=l"(out) : "f"(lo), "f"(hi))

#define UNPACK_F32X2(lo, hi, in) \
    asm("mov.b64 {%0, %1}, %2;" : "=f"(lo), "=f"(hi) : "l"(in))

#define FMA_F32X2(d, a, b, c) \
    asm("fma.rn.f32x2 %0, %1, %2, %3;" : "=l"(d) : "l"(a), "l"(b), "l"(c))

__global__ __launch_bounds__(TPB)
void chamfer_pass_kernel(const float* __restrict__ x, const float* __restrict__ y,
                         float* __restrict__ out) {
    const int bid = blockIdx.x;
    const float* own;
    const float* opp;
    int lbid;
    if (bid < BLOCKS_PER_DIR) { own = x; opp = y; lbid = bid; }
    else                      { own = y; opp = x; lbid = bid - BLOCKS_PER_DIR; }

    const int batch = lbid / CHUNKS_PER_BATCH;
    const int chunk = lbid % CHUNKS_PER_BATCH;
    const float* __restrict__ ownb = own + (size_t)batch * PTS * 3;
    const float* __restrict__ oppb = opp + (size_t)batch * PTS * 3;

    // Per j-pair: sAB = {(-2a0,-2a1),(-2b0,-2b1)}, sCN = {(-2c0,-2c1),(n0,n1)}
    __shared__ __align__(16) ulonglong2 sAB[JP];
    __shared__ __align__(16) ulonglong2 sCN[JP];

    const int tid = threadIdx.x;

    // Owned points: pre-broadcast each coordinate into both f32x2 lanes.
    float x0[RX], x1[RX], x2[RX];
    unsigned long long xa[RX], xb[RX], xc[RX];
    float mnl[RX], mnh[RX];
#pragma unroll
    for (int r = 0; r < RX; r++) {
        int i = chunk * CHUNK + r * TPB + tid;
        x0[r] = ownb[i * 3 + 0];
        x1[r] = ownb[i * 3 + 1];
        x2[r] = ownb[i * 3 + 2];
        PACK_F32X2(xa[r], x0[r], x0[r]);
        PACK_F32X2(xb[r], x1[r], x1[r]);
        PACK_F32X2(xc[r], x2[r], x2[r]);
        mnl[r] = 3.4e38f;
        mnh[r] = 3.4e38f;
    }

    for (int t0 = 0; t0 < PTS; t0 += TILE) {
        __syncthreads();
#pragma unroll
        for (int jj = tid; jj < TILE; jj += TPB) {
            float a = oppb[(t0 + jj) * 3 + 0];
            float b = oppb[(t0 + jj) * 3 + 1];
            float c = oppb[(t0 + jj) * 3 + 2];
            float n = fmaf(a, a, fmaf(b, b, c * c));
            int   jp = jj >> 1;
            int   lane = jj & 1;
            float* pab = (float*)&sAB[jp];
            float* pcn = (float*)&sCN[jp];
            pab[lane + 0] = -2.0f * a;
            pab[lane + 2] = -2.0f * b;
            pcn[lane + 0] = -2.0f * c;
            pcn[lane + 2] = n;
        }
        __syncthreads();

#pragma unroll 8
        for (int jp = 0; jp < JP; ++jp) {
            ulonglong2 ab = sAB[jp];   // .x = a-pair, .y = b-pair  (LDS.128)
            ulonglong2 cn = sCN[jp];   // .x = c-pair, .y = n-pair  (LDS.128)
#pragma unroll
            for (int r = 0; r < RX; ++r) {
                unsigned long long t;
                FMA_F32X2(t, xc[r], cn.x, cn.y);
                FMA_F32X2(t, xb[r], ab.y, t);
                FMA_F32X2(t, xa[r], ab.x, t);
                float lo, hi;
                UNPACK_F32X2(lo, hi, t);
                mnl[r] = fminf(mnl[r], lo);
                mnh[r] = fminf(mnh[r], hi);
            }
        }
    }

    // per-thread sum of (min_j + |x|^2)
    float s = 0.0f;
#pragma unroll
    for (int r = 0; r < RX; r++) {
        float xn = fmaf(x0[r], x0[r], fmaf(x1[r], x1[r], x2[r] * x2[r]));
        s += fminf(mnl[r], mnh[r]) + xn;
    }

    // deterministic block tree reduction
    __shared__ float red[TPB];
    red[tid] = s;
    __syncthreads();
#pragma unroll
    for (int off = TPB / 2; off > 0; off >>= 1) {
        if (tid < off) red[tid] += red[tid + off];
        __syncthreads();
    }
    if (tid == 0) g_part[bid] = red[0];

    // ticket-gated deterministic final reduction by last-finishing block
    __shared__ bool isLast;
    __threadfence();
    __syncthreads();
    if (tid == 0) {
        unsigned t = atomicAdd(&g_ticket, 1u);
        isLast = (t == gridDim.x - 1);
        if (isLast) g_ticket = 0;   // reset for next graph replay
    }
    __syncthreads();
    if (isLast) {
        float v = (tid < NBLOCKS) ? g_part[tid] : 0.0f;
        red[tid] = v;
        __syncthreads();
#pragma unroll
        for (int off = TPB / 2; off > 0; off >>= 1) {
            if (tid < off) red[tid] += red[tid + off];
            __syncthreads();
        }
        if (tid == 0) out[0] = red[0] / (float)(BATCH * PTS);
    }
}

extern "C" void kernel_launch(void* const* d_in, const int* in_sizes, int n_in,
                              void* d_out, int out_size) {
    const float* x = (const float*)d_in[0];
    const float* y = (const float*)d_in[1];
    float* out = (float*)d_out;

    chamfer_pass_kernel<<<NBLOCKS, TPB>>>(x, y, out);
}

// round 7
// speedup vs baseline: 3.8793x; 1.0883x over previous
#include <cuda_runtime.h>

// ChamferDistance: B=8, N=M=8192, D=3.
// min_j d = min_j (n_j + x . y'_j) + |x_i|^2,  y' = -2y folded into tile fill.
// Inner loop: packed fma.rn.f32x2, RX=8 owned points per thread, 4-way j-split
// so the grid stays at 256 blocks. Partial mins combined deterministically via
// per-group tickets; final scalar via global ticket. Single kernel launch.

#define TPB    256
#define RX     8
#define CHUNK  (TPB * RX)          // 2048 owned points per block
#define PTS    8192
#define BATCH  8
#define TILE   1024
#define JP     (TILE / 2)          // j-pairs per tile
#define NCHUNK (PTS / CHUNK)       // 4
#define NJS    4                   // j-split factor
#define JSEG   (PTS / NJS)         // 2048 opposing points per block
#define NGROUP (2 * BATCH * NCHUNK)   // 64
#define NBLOCKS (NGROUP * NJS)        // 256

__device__ float    g_pmin[NGROUP * NJS * CHUNK];
__device__ float    g_part[NGROUP];
__device__ unsigned g_gticket[NGROUP];
__device__ unsigned g_fticket;

#define PACK_F32X2(out, lo, hi) \
    asm("mov.b64 %0, {%1, %2};" : "=l"(out) : "f"(lo), "f"(hi))

#define UNPACK_F32X2(lo, hi, in) \
    asm("mov.b64 {%0, %1}, %2;" : "=f"(lo), "=f"(hi) : "l"(in))

#define FMA_F32X2(d, a, b, c) \
    asm("fma.rn.f32x2 %0, %1, %2, %3;" : "=l"(d) : "l"(a), "l"(b), "l"(c))

__global__ __launch_bounds__(TPB)
void chamfer_pass_kernel(const float* __restrict__ x, const float* __restrict__ y,
                         float* __restrict__ out) {
    const int bid   = blockIdx.x;
    const int dir   = bid >> 7;
    const int batch = (bid >> 4) & 7;
    const int chunk = (bid >> 2) & 3;
    const int js    = bid & 3;
    const int group = (dir * BATCH + batch) * NCHUNK + chunk;

    const float* __restrict__ ownb = (dir ? y : x) + (size_t)batch * PTS * 3;
    const float* __restrict__ oppb = (dir ? x : y) + (size_t)batch * PTS * 3;

    // Per j-pair: sAB = {(-2a0,-2a1),(-2b0,-2b1)}, sCN = {(-2c0,-2c1),(n0,n1)}
    __shared__ __align__(16) ulonglong2 sAB[JP];
    __shared__ __align__(16) ulonglong2 sCN[JP];

    const int tid = threadIdx.x;

    unsigned long long xa[RX], xb[RX], xc[RX];
    float mnl[RX], mnh[RX];
#pragma unroll
    for (int r = 0; r < RX; r++) {
        int i = chunk * CHUNK + r * TPB + tid;
        float a = ownb[i * 3 + 0];
        float b = ownb[i * 3 + 1];
        float c = ownb[i * 3 + 2];
        PACK_F32X2(xa[r], a, a);
        PACK_F32X2(xb[r], b, b);
        PACK_F32X2(xc[r], c, c);
        mnl[r] = 3.4e38f;
        mnh[r] = 3.4e38f;
    }

    const int jbase = js * JSEG;
    for (int t0 = 0; t0 < JSEG; t0 += TILE) {
        __syncthreads();
#pragma unroll
        for (int jj = tid; jj < TILE; jj += TPB) {
            const float* p = oppb + (size_t)(jbase + t0 + jj) * 3;
            float a = p[0], b = p[1], c = p[2];
            float n = fmaf(a, a, fmaf(b, b, c * c));
            int jp = jj >> 1, lane = jj & 1;
            float* pab = (float*)&sAB[jp];
            float* pcn = (float*)&sCN[jp];
            pab[lane + 0] = -2.0f * a;
            pab[lane + 2] = -2.0f * b;
            pcn[lane + 0] = -2.0f * c;
            pcn[lane + 2] = n;
        }
        __syncthreads();

#pragma unroll 4
        for (int jp = 0; jp < JP; ++jp) {
            ulonglong2 ab = sAB[jp];   // LDS.128 broadcast
            ulonglong2 cn = sCN[jp];   // LDS.128 broadcast
#pragma unroll
            for (int r = 0; r < RX; ++r) {
                unsigned long long t;
                FMA_F32X2(t, xc[r], cn.x, cn.y);
                FMA_F32X2(t, xb[r], ab.y, t);
                FMA_F32X2(t, xa[r], ab.x, t);
                float lo, hi;
                UNPACK_F32X2(lo, hi, t);
                mnl[r] = fminf(mnl[r], lo);
                mnh[r] = fminf(mnh[r], hi);
            }
        }
    }

    // publish this j-slice's partial mins
#pragma unroll
    for (int r = 0; r < RX; r++)
        g_pmin[(group * NJS + js) * CHUNK + r * TPB + tid] = fminf(mnl[r], mnh[r]);

    // per-group ticket: 4th arrival combines (fixed order -> deterministic)
    __shared__ bool isComb;
    __threadfence();
    __syncthreads();
    if (tid == 0) {
        unsigned t = atomicAdd(&g_gticket[group], 1u);
        isComb = (t == NJS - 1);
        if (isComb) g_gticket[group] = 0;   // reset for next replay
    }
    __syncthreads();
    if (!isComb) return;
    __threadfence();

    float s = 0.0f;
#pragma unroll
    for (int r = 0; r < RX; r++) {
        int idx = r * TPB + tid;
        float m = g_pmin[(group * NJS + 0) * CHUNK + idx];
        m = fminf(m, g_pmin[(group * NJS + 1) * CHUNK + idx]);
        m = fminf(m, g_pmin[(group * NJS + 2) * CHUNK + idx]);
        m = fminf(m, g_pmin[(group * NJS + 3) * CHUNK + idx]);
        float x0, x1, x2, d0, d1, d2;
        UNPACK_F32X2(x0, d0, xa[r]);
        UNPACK_F32X2(x1, d1, xb[r]);
        UNPACK_F32X2(x2, d2, xc[r]);
        s += m + fmaf(x0, x0, fmaf(x1, x1, x2 * x2));
    }

    __shared__ float red[TPB];
    red[tid] = s;
    __syncthreads();
#pragma unroll
    for (int o = TPB / 2; o > 0; o >>= 1) {
        if (tid < o) red[tid] += red[tid + o];
        __syncthreads();
    }
    if (tid == 0) g_part[group] = red[0];

    // global ticket over the 64 combiners: last one reduces the scalar
    __shared__ bool isFin;
    __threadfence();
    __syncthreads();
    if (tid == 0) {
        unsigned t = atomicAdd(&g_fticket, 1u);
        isFin = (t == NGROUP - 1);
        if (isFin) g_fticket = 0;   // reset for next replay
    }
    __syncthreads();
    if (!isFin) return;
    __threadfence();

    float v = (tid < NGROUP) ? g_part[tid] : 0.0f;
    red[tid] = v;
    __syncthreads();
#pragma unroll
    for (int o = TPB / 2; o > 0; o >>= 1) {
        if (tid < o) red[tid] += red[tid + o];
        __syncthreads();
    }
    if (tid == 0) out[0] = red[0] * (1.0f / 65536.0f);
}

extern "C" void kernel_launch(void* const* d_in, const int* in_sizes, int n_in,
                              void* d_out, int out_size) {
    const float* x = (const float*)d_in[0];
    const float* y = (const float*)d_in[1];
    float* out = (float*)d_out;

    chamfer_pass_kernel<<<NBLOCKS, TPB>>>(x, y, out);
}